// round 8
// baseline (speedup 1.0000x reference)
#include <cuda_runtime.h>
#include <cstdint>

#define NB   64
#define NPG  1024
#define NFEA 8
#define MIN_DIST 2.9f

#define TILE2    64
#define NCH2     (NPG / TILE2)                 // 16
#define NTRI2    (NCH2 * (NCH2 + 1) / 2)       // 136
#define CTHREADS 256
#define NBLOCKS2 ((NTRI2 + 1) * NB)            // 8768

typedef unsigned long long u64;

// sorted points per batch: (x, y, z, |p|^2), ascending in x
__device__ float4 g_pts[NB * NPG];

// partial slots — fully overwritten every launch (skipped tiles write 0)
__device__ float g_coll[NTRI2 * NB];     // 8704
__device__ float g_sb[NB][8];            // per batch: rsum, esum, ecnt, vol, field
__device__ unsigned int g_done = 0;      // last-block counter (self-resetting)

// ---------------- reduce helpers ----------------
__device__ __forceinline__ float wredSum(float v) {
#pragma unroll
    for (int o = 16; o; o >>= 1) v += __shfl_down_sync(0xffffffffu, v, o);
    return v;
}
__device__ __forceinline__ float wredMin(float v) {
#pragma unroll
    for (int o = 16; o; o >>= 1) v = fminf(v, __shfl_down_sync(0xffffffffu, v, o));
    return v;
}
__device__ __forceinline__ float wredMax(float v) {
#pragma unroll
    for (int o = 16; o; o >>= 1) v = fmaxf(v, __shfl_down_sync(0xffffffffu, v, o));
    return v;
}
__device__ __forceinline__ float blockSum(float v, float* sbuf) {
    const int lane = threadIdx.x & 31;
    const int wid  = threadIdx.x >> 5;
    v = wredSum(v);
    if (lane == 0) sbuf[wid] = v;
    __syncthreads();
    if (wid == 0) {
        v = (lane < 8) ? sbuf[lane] : 0.0f;
        v = wredSum(v);
        if (lane == 0) sbuf[0] = v;
    }
    __syncthreads();
    float r = sbuf[0];
    __syncthreads();
    return r;
}
__device__ __forceinline__ double blockSumD(double v, double* dbuf) {
    const int lane = threadIdx.x & 31;
    const int wid  = threadIdx.x >> 5;
#pragma unroll
    for (int o = 16; o; o >>= 1) v += __shfl_down_sync(0xffffffffu, v, o);
    if (lane == 0) dbuf[wid] = v;
    __syncthreads();
    if (wid == 0) {
        v = (lane < 8) ? dbuf[lane] : 0.0;
#pragma unroll
        for (int o = 16; o; o >>= 1) v += __shfl_down_sync(0xffffffffu, v, o);
        if (lane == 0) dbuf[0] = v;
    }
    __syncthreads();
    double r = dbuf[0];
    __syncthreads();
    return r;
}
__device__ __forceinline__ float sqrt_approx(float x) {
    float d; asm("sqrt.approx.f32 %0,%1;" : "=f"(d) : "f"(x)); return d;
}

// ---------------- sort kernel: per-batch bitonic sort by x ----------------
// grid = NB blocks, 256 threads. Key = (sortable_x << 32) | idx.
__global__ __launch_bounds__(256) void k_sort(const float* __restrict__ pred)
{
    __shared__ u64 skey[NPG];
    const int b = blockIdx.x;
    const int t = threadIdx.x;

#pragma unroll
    for (int k = 0; k < 4; k++) {
        const int idx = t + k * 256;
        const float x = pred[3 * (size_t)(b * NPG + idx)];
        unsigned int u = __float_as_uint(x);
        u = (u >> 31) ? ~u : (u | 0x80000000u);
        skey[idx] = ((u64)u << 32) | (unsigned)idx;
    }
    __syncthreads();

    for (unsigned int ks = 2; ks <= NPG; ks <<= 1) {
        for (unsigned int j = ks >> 1; j > 0; j >>= 1) {
#pragma unroll
            for (int m = 0; m < 4; m++) {
                const int i = t + m * 256;
                const int ixj = i ^ (int)j;
                if (ixj > i) {
                    const u64 a = skey[i];
                    const u64 c = skey[ixj];
                    const bool up = ((i & ks) == 0);
                    if ((a > c) == up) { skey[i] = c; skey[ixj] = a; }
                }
            }
            __syncthreads();
        }
    }

    // gather sorted points, precompute |p|^2
#pragma unroll
    for (int k = 0; k < 4; k++) {
        const int idx = t + k * 256;
        const int id  = (int)(skey[idx] & 0xFFFFFFFFu);
        const float* p = pred + 3 * (size_t)(b * NPG + id);
        const float x = p[0], y = p[1], z = p[2];
        g_pts[b * NPG + idx] = make_float4(x, y, z, fmaf(x, x, fmaf(y, y, z * z)));
    }
}

// ---------------- fused kernel ----------------
// grid (NTRI2+1, NB), 256 threads.
//   bx < 136 : sorted collapse tile-pair (ic >= jc), pruned by x-gap
//   bx == 136: stats block of batch b
__global__ __launch_bounds__(CTHREADS) void k_fused(
    const float* __restrict__ pred,
    const float* __restrict__ tru,
    const float* __restrict__ org,
    const float* __restrict__ nfeat,
    float* __restrict__ out, int out_size)
{
    __shared__ float4 sj[TILE2];
    __shared__ float  sred[8];
    __shared__ float  sq[16][8];
    __shared__ double dbuf[8];
    __shared__ bool   amLast;

    const int b  = blockIdx.y;
    const int bx = blockIdx.x;
    const int t  = threadIdx.x;
    const int lane = t & 31;
    const int wid  = t >> 5;

    if (bx < NTRI2) {
        // decode triangle index: bx = ic*(ic+1)/2 + jc, ic >= jc
        int ic = (int)((sqrtf(8.0f * bx + 1.0f) - 1.0f) * 0.5f);
        while ((ic + 1) * (ic + 2) / 2 <= bx) ic++;
        while (ic * (ic + 1) / 2 > bx) ic--;
        const int jc = bx - ic * (ic + 1) / 2;

        const float4* __restrict__ P = g_pts + (size_t)b * NPG;
        const int ibase = ic * TILE2;
        const int jbase = jc * TILE2;

        // exact prune: sorted x -> min of tile ic at ibase, max of tile jc at jbase+63
        const bool skip = (ic != jc) && (P[ibase].x - P[jbase + TILE2 - 1].x >= MIN_DIST);

        float S = 0.0f;
        if (!skip) {
            if (t < TILE2) sj[t] = P[jbase + t];

            // 2 i-rows per thread (lane, lane+32), 8-j slice per warp
            const int r   = lane;
            const int jlo = wid * 8;

            float m2x[2], m2y[2], m2z[2], si[2];
#pragma unroll
            for (int k = 0; k < 2; k++) {
                const float4 pi = P[ibase + r + 32 * k];
                si[k]  = pi.w;
                m2x[k] = -2.0f * pi.x;
                m2y[k] = -2.0f * pi.y;
                m2z[k] = -2.0f * pi.z;
            }
            __syncthreads();

            float acc0 = 0.0f, acc1 = 0.0f;
#pragma unroll
            for (int m = 0; m < 8; m++) {
                const float4 q = sj[jlo + m];
                {
                    const float d2 = fmaf(m2x[0], q.x,
                                     fmaf(m2y[0], q.y,
                                     fmaf(m2z[0], q.z, si[0] + q.w)));
                    const float d  = sqrt_approx(d2);   // d2<0 -> NaN -> relu 0
                    const float e  = fmaxf(MIN_DIST - d, 0.0f);
                    acc0 = fmaf(e, e, acc0);
                }
                {
                    const float d2 = fmaf(m2x[1], q.x,
                                     fmaf(m2y[1], q.y,
                                     fmaf(m2z[1], q.z, si[1] + q.w)));
                    const float d  = sqrt_approx(d2);
                    const float e  = fmaxf(MIN_DIST - d, 0.0f);
                    acc1 = fmaf(e, e, acc1);
                }
            }
            float a = acc0 + acc1;

            // diagonal tile: remove self-pairs (identical instruction sequence)
            if (ic == jc) {
#pragma unroll
                for (int k = 0; k < 2; k++) {
                    const int i  = r + 32 * k;
                    const int jj = i - jlo;
                    if (jj >= 0 && jj < 8) {
                        const float4 q = sj[i];
                        const float d2 = fmaf(m2x[k], q.x,
                                         fmaf(m2y[k], q.y,
                                         fmaf(m2z[k], q.z, si[k] + q.w)));
                        const float d  = sqrt_approx(d2);
                        const float e  = fmaxf(MIN_DIST - d, 0.0f);
                        a = fmaf(-e, e, a);
                    }
                }
            }
            S = blockSum(a, sred);
        }
        if (t == 0)
            g_coll[b * NTRI2 + bx] = skip ? 0.0f : ((ic != jc) ? 2.0f * S : S);
    } else {
        // ======================= stats =======================
        float px[4], py[4], pz[4], ox[4], oy[4], oz[4];
        float rsum = 0.0f;
#pragma unroll
        for (int k = 0; k < 4; k++) {
            const int idx = b * NPG + t + k * 256;
            const float* pp = pred + 3 * idx;
            const float* tt = tru  + 3 * idx;
            const float* oo = org  + 3 * idx;
            px[k] = pp[0]; py[k] = pp[1]; pz[k] = pp[2];
            const float dx = px[k] - tt[0];
            const float dy = py[k] - tt[1];
            const float dz = pz[k] - tt[2];
            rsum += dx * dx + dy * dy + dz * dz;
            ox[k] = oo[0]; oy[k] = oo[1]; oz[k] = oo[2];
        }

        float lv[14];
        lv[0]  = fminf(fminf(px[0], px[1]), fminf(px[2], px[3]));
        lv[1]  = fmaxf(fmaxf(px[0], px[1]), fmaxf(px[2], px[3]));
        lv[2]  = fminf(fminf(py[0], py[1]), fminf(py[2], py[3]));
        lv[3]  = fmaxf(fmaxf(py[0], py[1]), fmaxf(py[2], py[3]));
        lv[4]  = fminf(fminf(pz[0], pz[1]), fminf(pz[2], pz[3]));
        lv[5]  = fmaxf(fmaxf(pz[0], pz[1]), fmaxf(pz[2], pz[3]));
        lv[6]  = fminf(fminf(ox[0], ox[1]), fminf(ox[2], ox[3]));
        lv[7]  = fmaxf(fmaxf(ox[0], ox[1]), fmaxf(ox[2], ox[3]));
        lv[8]  = fminf(fminf(oy[0], oy[1]), fminf(oy[2], oy[3]));
        lv[9]  = fmaxf(fmaxf(oy[0], oy[1]), fmaxf(oy[2], oy[3]));
        lv[10] = fminf(fminf(oz[0], oz[1]), fminf(oz[2], oz[3]));
        lv[11] = fmaxf(fmaxf(oz[0], oz[1]), fmaxf(oz[2], oz[3]));
        lv[12] = pz[0] + pz[1] + pz[2] + pz[3];
        lv[13] = rsum;

#pragma unroll
        for (int i = 0; i < 14; i++) {
            float v;
            if (i < 12) v = (i & 1) ? wredMax(lv[i]) : wredMin(lv[i]);
            else        v = wredSum(lv[i]);
            if (lane == 0) sq[i][wid] = v;
        }
        __syncthreads();
        if (t < 14) {
            float a = sq[t][0];
            const bool isMin = (t < 12) && !(t & 1);
            const bool isMax = (t < 12) &&  (t & 1);
#pragma unroll
            for (int w = 1; w < 8; w++) {
                const float u = sq[t][w];
                a = isMin ? fminf(a, u) : (isMax ? fmaxf(a, u) : (a + u));
            }
            sq[t][0] = a;
        }
        __syncthreads();

        const float OMNZ = sq[10][0], OMXZ = sq[11][0];
        const float zr   = __fsub_rn(OMXZ, OMNZ);
        const float thlo = __fadd_rn(OMNZ, __fmul_rn(0.15f, zr));
        const float thhi = __fsub_rn(OMXZ, __fmul_rn(0.15f, zr));

        float esum = 0.0f, ecnt = 0.0f;
#pragma unroll
        for (int k = 0; k < 4; k++) {
            const bool m = (oz[k] <= thlo) || (oz[k] >= thhi);
            if (m) {
                const float dx = px[k] - ox[k];
                const float dy = py[k] - oy[k];
                const float dz = pz[k] - oz[k];
                esum += dx * dx + dy * dy + dz * dz;
                ecnt += 1.0f;
            }
        }
        esum = wredSum(esum);
        ecnt = wredSum(ecnt);
        if (lane == 0) { sq[14][wid] = esum; sq[15][wid] = ecnt; }
        __syncthreads();

        if (t == 0) {
            float ES = 0.0f, EC = 0.0f;
#pragma unroll
            for (int w = 0; w < 8; w++) { ES += sq[14][w]; EC += sq[15][w]; }

            const float pdx = sq[1][0] - sq[0][0];
            const float pdy = sq[3][0] - sq[2][0];
            const float pdz = sq[5][0] - sq[4][0];
            const float odx = sq[7][0] - sq[6][0];
            const float ody = sq[9][0] - sq[8][0];
            const float odz = OMXZ - OMNZ;
            const float rx = (pdx - odx) / (odx + 1e-8f);
            const float ry = (pdy - ody) / (ody + 1e-8f);
            const float rz = (pdz - odz) / (odz + 1e-8f);
            const float xy_pen = fmaxf(rx - 0.02f, 0.0f) + fmaxf(ry - 0.02f, 0.0f);
            const float z_pen  = fmaxf(rz, 0.0f);

            const float zcom  = sq[12][0] * (1.0f / 1024.0f);
            const float znorm = (zcom - sq[4][0]) / ((sq[5][0] - sq[4][0]) + 1e-8f);
            const float v = nfeat[(size_t)b * NPG * NFEA + (NFEA - 3)];
            const float target = (v > 0.0f) ? 0.6f : 0.4f;
            const float dvz = znorm - target;
            const float contrib = (fabsf(v) >= 1e-6f) ? dvz * dvz : 0.0f;

            g_sb[b][0] = sq[13][0];
            g_sb[b][1] = ES;
            g_sb[b][2] = EC;
            g_sb[b][3] = xy_pen + 2.0f * z_pen;
            g_sb[b][4] = contrib;
        }
        __syncthreads();
    }

    // ======================= last-block finalize =======================
    __threadfence();
    if (t == 0) {
        const unsigned int ret = atomicAdd(&g_done, 1u);
        amLast = (ret == (unsigned)(NBLOCKS2 - 1));
    }
    __syncthreads();

    if (amLast) {
        __threadfence();   // acquire

        double cs = 0.0;
#pragma unroll
        for (int k = 0; k < NTRI2 * NB / 256; k++)   // 34
            cs += (double)g_coll[t + k * 256];
        const double COLL = blockSumD(cs, dbuf);

        double r = 0.0, e = 0.0, c = 0.0, vo = 0.0, f = 0.0;
        if (t < NB) {
            r  = (double)g_sb[t][0];
            e  = (double)g_sb[t][1];
            c  = (double)g_sb[t][2];
            vo = (double)g_sb[t][3];
            f  = (double)g_sb[t][4];
        }
        const double RSUM = blockSumD(r,  dbuf);
        const double ESUM = blockSumD(e,  dbuf);
        const double ECNT = blockSumD(c,  dbuf);
        const double VSUM = blockSumD(vo, dbuf);
        const double FSUM = blockSumD(f,  dbuf);

        if (t == 0) {
            const double recon  = RSUM / (double)(NB * NPG * 3);
            const double volume = VSUM / (double)NB;
            const double elec   = ESUM / (ECNT * 3.0);
            const double coll   = COLL / ((double)NB * (double)NPG * (double)(NPG - 1));
            const double field  = FSUM / (double)NB;
            const double total  = 1.0 * recon + 10.0 * volume + 50.0 * elec
                                + 5.0 * coll + 2.0 * field;
            double vals[6] = { total, recon, volume, elec, coll, field };
            for (int i = 0; i < 6 && i < out_size; i++) out[i] = (float)vals[i];
            g_done = 0;   // reset for next replay
        }
    }
}

extern "C" void kernel_launch(void* const* d_in, const int* in_sizes, int n_in,
                              void* d_out, int out_size)
{
    int coord_idx[3]; int n_coord = 0;
    int nf_idx = -1, bv_idx = -1;
    for (int i = 0; i < n_in; i++) {
        if (in_sizes[i] == NB * NPG * 3) { if (n_coord < 3) coord_idx[n_coord] = i; n_coord++; }
        else if (in_sizes[i] == NB * NPG * NFEA) nf_idx = i;
        else if (in_sizes[i] == NB * NPG) bv_idx = i;
    }

    const float *pred, *tru, *org, *nf;
    if (n_coord == 3 && nf_idx >= 0) {
        if (bv_idx >= 0 && bv_idx < coord_idx[0]) {
            org  = (const float*)d_in[coord_idx[0]];
            pred = (const float*)d_in[coord_idx[1]];
            tru  = (const float*)d_in[coord_idx[2]];
        } else {
            pred = (const float*)d_in[coord_idx[0]];
            tru  = (const float*)d_in[coord_idx[1]];
            org  = (const float*)d_in[coord_idx[2]];
        }
        nf = (const float*)d_in[nf_idx];
    } else {
        pred = (const float*)d_in[0];
        tru  = (const float*)d_in[1];
        org  = (const float*)d_in[2];
        nf   = (const float*)d_in[3];
    }

    k_sort<<<NB, 256>>>(pred);
    k_fused<<<dim3(NTRI2 + 1, NB), CTHREADS>>>(pred, tru, org, nf,
                                               (float*)d_out, out_size);
}

// round 9
// speedup vs baseline: 1.3030x; 1.3030x over previous
#include <cuda_runtime.h>
#include <cstdint>

#define NB   64
#define NPG  1024
#define NFEA 8
#define MIN_DIST 2.9f

#define TILE     128
#define NCHUNK   (NPG / TILE)                  // 8
#define NTRI     (NCHUNK * (NCHUNK + 1) / 2)   // 36
#define CTHREADS 256
#define NBLOCKS  ((NTRI + 1) * NB)             // 2368
#define JSLICE   16

typedef unsigned long long u64;

// triangle tile decode tables (ic >= jc)
__device__ const signed char TIC[NTRI] =
    {0,1,1,2,2,2,3,3,3,3,4,4,4,4,4,5,5,5,5,5,5,
     6,6,6,6,6,6,6,7,7,7,7,7,7,7,7};
__device__ const signed char TJC[NTRI] =
    {0,0,1,0,1,2,0,1,2,3,0,1,2,3,4,0,1,2,3,4,5,
     0,1,2,3,4,5,6,0,1,2,3,4,5,6,7};

// sorted points per batch: (x, y, z, |p|^2), ascending x
__device__ float4 g_pts[NB * NPG];

// partial slots — fully overwritten every launch (skipped tiles write 0)
__device__ float g_coll[NTRI * NB];      // 2304
__device__ float g_sb[NB][8];
__device__ unsigned int g_done = 0;

// ---------------- reduce helpers ----------------
__device__ __forceinline__ float wredSum(float v) {
#pragma unroll
    for (int o = 16; o; o >>= 1) v += __shfl_down_sync(0xffffffffu, v, o);
    return v;
}
__device__ __forceinline__ float wredMin(float v) {
#pragma unroll
    for (int o = 16; o; o >>= 1) v = fminf(v, __shfl_down_sync(0xffffffffu, v, o));
    return v;
}
__device__ __forceinline__ float wredMax(float v) {
#pragma unroll
    for (int o = 16; o; o >>= 1) v = fmaxf(v, __shfl_down_sync(0xffffffffu, v, o));
    return v;
}
__device__ __forceinline__ float blockSum(float v, float* sbuf) {
    const int lane = threadIdx.x & 31;
    const int wid  = threadIdx.x >> 5;
    v = wredSum(v);
    if (lane == 0) sbuf[wid] = v;
    __syncthreads();
    if (wid == 0) {
        v = (lane < 8) ? sbuf[lane] : 0.0f;
        v = wredSum(v);
        if (lane == 0) sbuf[0] = v;
    }
    __syncthreads();
    float r = sbuf[0];
    __syncthreads();
    return r;
}
__device__ __forceinline__ double blockSumD(double v, double* dbuf) {
    const int lane = threadIdx.x & 31;
    const int wid  = threadIdx.x >> 5;
#pragma unroll
    for (int o = 16; o; o >>= 1) v += __shfl_down_sync(0xffffffffu, v, o);
    if (lane == 0) dbuf[wid] = v;
    __syncthreads();
    if (wid == 0) {
        v = (lane < 8) ? dbuf[lane] : 0.0;
#pragma unroll
        for (int o = 16; o; o >>= 1) v += __shfl_down_sync(0xffffffffu, v, o);
        if (lane == 0) dbuf[0] = v;
    }
    __syncthreads();
    double r = dbuf[0];
    __syncthreads();
    return r;
}
__device__ __forceinline__ float sqrt_approx(float x) {
    float d; asm("sqrt.approx.f32 %0,%1;" : "=f"(d) : "f"(x)); return d;
}

// ---------------- sort kernel: per-batch bitonic sort by x ----------------
__global__ __launch_bounds__(256) void k_sort(const float* __restrict__ pred)
{
    __shared__ u64 skey[NPG];
    const int b = blockIdx.x;
    const int t = threadIdx.x;

#pragma unroll
    for (int k = 0; k < 4; k++) {
        const int idx = t + k * 256;
        const float x = pred[3 * (size_t)(b * NPG + idx)];
        unsigned int u = __float_as_uint(x);
        u = (u >> 31) ? ~u : (u | 0x80000000u);
        skey[idx] = ((u64)u << 32) | (unsigned)idx;
    }
    __syncthreads();

    for (unsigned int ks = 2; ks <= NPG; ks <<= 1) {
        for (unsigned int j = ks >> 1; j > 0; j >>= 1) {
#pragma unroll
            for (int m = 0; m < 4; m++) {
                const int i = t + m * 256;
                const int ixj = i ^ (int)j;
                if (ixj > i) {
                    const u64 a = skey[i];
                    const u64 c = skey[ixj];
                    const bool up = ((i & ks) == 0);
                    if ((a > c) == up) { skey[i] = c; skey[ixj] = a; }
                }
            }
            __syncthreads();
        }
    }

#pragma unroll
    for (int k = 0; k < 4; k++) {
        const int idx = t + k * 256;
        const int id  = (int)(skey[idx] & 0xFFFFFFFFu);
        const float* p = pred + 3 * (size_t)(b * NPG + id);
        const float x = p[0], y = p[1], z = p[2];
        g_pts[b * NPG + idx] = make_float4(x, y, z, fmaf(x, x, fmaf(y, y, z * z)));
    }
}

// ---------------- fused kernel ----------------
// grid (NTRI+1, NB), 256 threads.
//   bx < 36 : sorted collapse tile (ic,jc), 128x128, pruned by exact x-gap
//   bx == 36: stats block of batch b
__global__ __launch_bounds__(CTHREADS) void k_fused(
    const float* __restrict__ pred,
    const float* __restrict__ tru,
    const float* __restrict__ org,
    const float* __restrict__ nfeat,
    float* __restrict__ out, int out_size)
{
    __shared__ float4 sj[TILE];
    __shared__ float  sred[8];
    __shared__ float  sq[16][8];
    __shared__ double dbuf[8];
    __shared__ bool   amLast;

    const int b  = blockIdx.y;
    const int bx = blockIdx.x;
    const int t  = threadIdx.x;
    const int lane = t & 31;
    const int wid  = t >> 5;

    if (bx < NTRI) {
        const int ic = TIC[bx];
        const int jc = TJC[bx];
        const float4* __restrict__ P = g_pts + (size_t)b * NPG;
        const int ibase = ic * TILE;
        const int jbase = jc * TILE;

        // exact prune (sorted x): min-x of tile ic vs max-x of tile jc
        const bool skip = (ic != jc) &&
                          (P[ibase].x - P[jbase + TILE - 1].x >= MIN_DIST);

        float S = 0.0f;
        if (!skip) {
            if (t < TILE) sj[t] = P[jbase + t];

            const int r   = lane;
            const int jlo = wid * JSLICE;

            float m2x[4], m2y[4], m2z[4], si[4];
#pragma unroll
            for (int k = 0; k < 4; k++) {
                const float4 pi = P[ibase + r + 32 * k];
                si[k]  = pi.w;
                m2x[k] = -2.0f * pi.x;
                m2y[k] = -2.0f * pi.y;
                m2z[k] = -2.0f * pi.z;
            }
            __syncthreads();

            float acc[4] = {0.0f, 0.0f, 0.0f, 0.0f};
#pragma unroll
            for (int m = 0; m < JSLICE; m++) {
                const float4 q = sj[jlo + m];
#pragma unroll
                for (int k = 0; k < 4; k++) {
                    const float d2 = fmaf(m2x[k], q.x,
                                     fmaf(m2y[k], q.y,
                                     fmaf(m2z[k], q.z, si[k] + q.w)));
                    const float d  = sqrt_approx(d2);   // d2<0 -> NaN -> relu 0
                    const float e  = fmaxf(MIN_DIST - d, 0.0f);
                    acc[k] = fmaf(e, e, acc[k]);
                }
            }
            float a = (acc[0] + acc[1]) + (acc[2] + acc[3]);

            // diagonal: remove self-pairs (identical instruction sequence)
            if (ic == jc) {
#pragma unroll
                for (int k = 0; k < 4; k++) {
                    const int i  = r + 32 * k;
                    const int jj = i - jlo;
                    if (jj >= 0 && jj < JSLICE) {
                        const float4 q = sj[i];
                        const float d2 = fmaf(m2x[k], q.x,
                                         fmaf(m2y[k], q.y,
                                         fmaf(m2z[k], q.z, si[k] + q.w)));
                        const float d  = sqrt_approx(d2);
                        const float e  = fmaxf(MIN_DIST - d, 0.0f);
                        a = fmaf(-e, e, a);
                    }
                }
            }
            S = blockSum(a, sred);
        }
        if (t == 0)
            g_coll[b * NTRI + bx] = skip ? 0.0f : ((ic != jc) ? 2.0f * S : S);
    } else {
        // ======================= stats =======================
        float px[4], py[4], pz[4], ox[4], oy[4], oz[4];
        float rsum = 0.0f;
#pragma unroll
        for (int k = 0; k < 4; k++) {
            const int idx = b * NPG + t + k * 256;
            const float* pp = pred + 3 * idx;
            const float* tt = tru  + 3 * idx;
            const float* oo = org  + 3 * idx;
            px[k] = pp[0]; py[k] = pp[1]; pz[k] = pp[2];
            const float dx = px[k] - tt[0];
            const float dy = py[k] - tt[1];
            const float dz = pz[k] - tt[2];
            rsum += dx * dx + dy * dy + dz * dz;
            ox[k] = oo[0]; oy[k] = oo[1]; oz[k] = oo[2];
        }

        float lv[14];
        lv[0]  = fminf(fminf(px[0], px[1]), fminf(px[2], px[3]));
        lv[1]  = fmaxf(fmaxf(px[0], px[1]), fmaxf(px[2], px[3]));
        lv[2]  = fminf(fminf(py[0], py[1]), fminf(py[2], py[3]));
        lv[3]  = fmaxf(fmaxf(py[0], py[1]), fmaxf(py[2], py[3]));
        lv[4]  = fminf(fminf(pz[0], pz[1]), fminf(pz[2], pz[3]));
        lv[5]  = fmaxf(fmaxf(pz[0], pz[1]), fmaxf(pz[2], pz[3]));
        lv[6]  = fminf(fminf(ox[0], ox[1]), fminf(ox[2], ox[3]));
        lv[7]  = fmaxf(fmaxf(ox[0], ox[1]), fmaxf(ox[2], ox[3]));
        lv[8]  = fminf(fminf(oy[0], oy[1]), fminf(oy[2], oy[3]));
        lv[9]  = fmaxf(fmaxf(oy[0], oy[1]), fmaxf(oy[2], oy[3]));
        lv[10] = fminf(fminf(oz[0], oz[1]), fminf(oz[2], oz[3]));
        lv[11] = fmaxf(fmaxf(oz[0], oz[1]), fmaxf(oz[2], oz[3]));
        lv[12] = pz[0] + pz[1] + pz[2] + pz[3];
        lv[13] = rsum;

#pragma unroll
        for (int i = 0; i < 14; i++) {
            float v;
            if (i < 12) v = (i & 1) ? wredMax(lv[i]) : wredMin(lv[i]);
            else        v = wredSum(lv[i]);
            if (lane == 0) sq[i][wid] = v;
        }
        __syncthreads();
        if (t < 14) {
            float a = sq[t][0];
            const bool isMin = (t < 12) && !(t & 1);
            const bool isMax = (t < 12) &&  (t & 1);
#pragma unroll
            for (int w = 1; w < 8; w++) {
                const float u = sq[t][w];
                a = isMin ? fminf(a, u) : (isMax ? fmaxf(a, u) : (a + u));
            }
            sq[t][0] = a;
        }
        __syncthreads();

        const float OMNZ = sq[10][0], OMXZ = sq[11][0];
        const float zr   = __fsub_rn(OMXZ, OMNZ);
        const float thlo = __fadd_rn(OMNZ, __fmul_rn(0.15f, zr));
        const float thhi = __fsub_rn(OMXZ, __fmul_rn(0.15f, zr));

        float esum = 0.0f, ecnt = 0.0f;
#pragma unroll
        for (int k = 0; k < 4; k++) {
            const bool m = (oz[k] <= thlo) || (oz[k] >= thhi);
            if (m) {
                const float dx = px[k] - ox[k];
                const float dy = py[k] - oy[k];
                const float dz = pz[k] - oz[k];
                esum += dx * dx + dy * dy + dz * dz;
                ecnt += 1.0f;
            }
        }
        esum = wredSum(esum);
        ecnt = wredSum(ecnt);
        if (lane == 0) { sq[14][wid] = esum; sq[15][wid] = ecnt; }
        __syncthreads();

        if (t == 0) {
            float ES = 0.0f, EC = 0.0f;
#pragma unroll
            for (int w = 0; w < 8; w++) { ES += sq[14][w]; EC += sq[15][w]; }

            const float pdx = sq[1][0] - sq[0][0];
            const float pdy = sq[3][0] - sq[2][0];
            const float pdz = sq[5][0] - sq[4][0];
            const float odx = sq[7][0] - sq[6][0];
            const float ody = sq[9][0] - sq[8][0];
            const float odz = OMXZ - OMNZ;
            const float rx = (pdx - odx) / (odx + 1e-8f);
            const float ry = (pdy - ody) / (ody + 1e-8f);
            const float rz = (pdz - odz) / (odz + 1e-8f);
            const float xy_pen = fmaxf(rx - 0.02f, 0.0f) + fmaxf(ry - 0.02f, 0.0f);
            const float z_pen  = fmaxf(rz, 0.0f);

            const float zcom  = sq[12][0] * (1.0f / 1024.0f);
            const float znorm = (zcom - sq[4][0]) / ((sq[5][0] - sq[4][0]) + 1e-8f);
            const float v = nfeat[(size_t)b * NPG * NFEA + (NFEA - 3)];
            const float target = (v > 0.0f) ? 0.6f : 0.4f;
            const float dvz = znorm - target;
            const float contrib = (fabsf(v) >= 1e-6f) ? dvz * dvz : 0.0f;

            g_sb[b][0] = sq[13][0];
            g_sb[b][1] = ES;
            g_sb[b][2] = EC;
            g_sb[b][3] = xy_pen + 2.0f * z_pen;
            g_sb[b][4] = contrib;
        }
        __syncthreads();
    }

    // ======================= last-block finalize =======================
    __threadfence();
    if (t == 0) {
        const unsigned int ret = atomicAdd(&g_done, 1u);
        amLast = (ret == (unsigned)(NBLOCKS - 1));
    }
    __syncthreads();

    if (amLast) {
        __threadfence();

        double cs = 0.0;
#pragma unroll
        for (int k = 0; k < 9; k++) cs += (double)g_coll[t + k * 256];   // 2304
        const double COLL = blockSumD(cs, dbuf);

        double r = 0.0, e = 0.0, c = 0.0, vo = 0.0, f = 0.0;
        if (t < NB) {
            r  = (double)g_sb[t][0];
            e  = (double)g_sb[t][1];
            c  = (double)g_sb[t][2];
            vo = (double)g_sb[t][3];
            f  = (double)g_sb[t][4];
        }
        const double RSUM = blockSumD(r,  dbuf);
        const double ESUM = blockSumD(e,  dbuf);
        const double ECNT = blockSumD(c,  dbuf);
        const double VSUM = blockSumD(vo, dbuf);
        const double FSUM = blockSumD(f,  dbuf);

        if (t == 0) {
            const double recon  = RSUM / (double)(NB * NPG * 3);
            const double volume = VSUM / (double)NB;
            const double elec   = ESUM / (ECNT * 3.0);
            const double coll   = COLL / ((double)NB * (double)NPG * (double)(NPG - 1));
            const double field  = FSUM / (double)NB;
            const double total  = 1.0 * recon + 10.0 * volume + 50.0 * elec
                                + 5.0 * coll + 2.0 * field;
            double vals[6] = { total, recon, volume, elec, coll, field };
            for (int i = 0; i < 6 && i < out_size; i++) out[i] = (float)vals[i];
            g_done = 0;
        }
    }
}

extern "C" void kernel_launch(void* const* d_in, const int* in_sizes, int n_in,
                              void* d_out, int out_size)
{
    int coord_idx[3]; int n_coord = 0;
    int nf_idx = -1, bv_idx = -1;
    for (int i = 0; i < n_in; i++) {
        if (in_sizes[i] == NB * NPG * 3) { if (n_coord < 3) coord_idx[n_coord] = i; n_coord++; }
        else if (in_sizes[i] == NB * NPG * NFEA) nf_idx = i;
        else if (in_sizes[i] == NB * NPG) bv_idx = i;
    }

    const float *pred, *tru, *org, *nf;
    if (n_coord == 3 && nf_idx >= 0) {
        if (bv_idx >= 0 && bv_idx < coord_idx[0]) {
            org  = (const float*)d_in[coord_idx[0]];
            pred = (const float*)d_in[coord_idx[1]];
            tru  = (const float*)d_in[coord_idx[2]];
        } else {
            pred = (const float*)d_in[coord_idx[0]];
            tru  = (const float*)d_in[coord_idx[1]];
            org  = (const float*)d_in[coord_idx[2]];
        }
        nf = (const float*)d_in[nf_idx];
    } else {
        pred = (const float*)d_in[0];
        tru  = (const float*)d_in[1];
        org  = (const float*)d_in[2];
        nf   = (const float*)d_in[3];
    }

    k_sort<<<NB, 256>>>(pred);
    k_fused<<<dim3(NTRI + 1, NB), CTHREADS>>>(pred, tru, org, nf,
                                              (float*)d_out, out_size);
}

// round 10
// speedup vs baseline: 1.6301x; 1.2510x over previous
#include <cuda_runtime.h>
#include <cstdint>

#define NB   64
#define NPG  1024
#define NFEA 8
#define MIN_DIST 2.9f

#define TILE     128
#define NTRI     36
#define CTHREADS 256
#define JSLICE   16

#define GRIDB    740                   // 5 blocks/SM * 148 SMs = one wave
#define NJOBS    (64 + NTRI * NB)      // 2368 = 64 stats + 2304 tiles

// triangle tile decode tables (ic >= jc)
__device__ const signed char TIC[NTRI] =
    {0,1,1,2,2,2,3,3,3,3,4,4,4,4,4,5,5,5,5,5,5,
     6,6,6,6,6,6,6,7,7,7,7,7,7,7,7};
__device__ const signed char TJC[NTRI] =
    {0,0,1,0,1,2,0,1,2,3,0,1,2,3,4,0,1,2,3,4,5,
     0,1,2,3,4,5,6,0,1,2,3,4,5,6,7};

// partial slots — fully overwritten every launch
__device__ float g_coll[NTRI * NB];      // 2304
__device__ float g_sb[NB][8];
__device__ unsigned int g_done = 0;

// ---------------- reduce helpers ----------------
__device__ __forceinline__ float wredSum(float v) {
#pragma unroll
    for (int o = 16; o; o >>= 1) v += __shfl_down_sync(0xffffffffu, v, o);
    return v;
}
__device__ __forceinline__ float wredMin(float v) {
#pragma unroll
    for (int o = 16; o; o >>= 1) v = fminf(v, __shfl_down_sync(0xffffffffu, v, o));
    return v;
}
__device__ __forceinline__ float wredMax(float v) {
#pragma unroll
    for (int o = 16; o; o >>= 1) v = fmaxf(v, __shfl_down_sync(0xffffffffu, v, o));
    return v;
}
__device__ __forceinline__ float blockSum(float v, float* sbuf) {
    const int lane = threadIdx.x & 31;
    const int wid  = threadIdx.x >> 5;
    v = wredSum(v);
    if (lane == 0) sbuf[wid] = v;
    __syncthreads();
    if (wid == 0) {
        v = (lane < 8) ? sbuf[lane] : 0.0f;
        v = wredSum(v);
        if (lane == 0) sbuf[0] = v;
    }
    __syncthreads();
    float r = sbuf[0];
    __syncthreads();
    return r;
}
__device__ __forceinline__ double blockSumD(double v, double* dbuf) {
    const int lane = threadIdx.x & 31;
    const int wid  = threadIdx.x >> 5;
#pragma unroll
    for (int o = 16; o; o >>= 1) v += __shfl_down_sync(0xffffffffu, v, o);
    if (lane == 0) dbuf[wid] = v;
    __syncthreads();
    if (wid == 0) {
        v = (lane < 8) ? dbuf[lane] : 0.0;
#pragma unroll
        for (int o = 16; o; o >>= 1) v += __shfl_down_sync(0xffffffffu, v, o);
        if (lane == 0) dbuf[0] = v;
    }
    __syncthreads();
    double r = dbuf[0];
    __syncthreads();
    return r;
}
__device__ __forceinline__ float sqrt_approx(float x) {
    float d; asm("sqrt.approx.f32 %0,%1;" : "=f"(d) : "f"(x)); return d;
}

// ---------------- mega kernel: all jobs, one wave ----------------
// job < 64          : stats for batch = job
// job >= 64         : triangle tile s = (job-64) % 36 of batch (job-64) / 36
__global__ __launch_bounds__(CTHREADS, 5) void k_mega(
    const float* __restrict__ pred,
    const float* __restrict__ tru,
    const float* __restrict__ org,
    const float* __restrict__ nfeat,
    float* __restrict__ out, int out_size)
{
    __shared__ float4 sj[TILE];
    __shared__ float  sred[8];
    __shared__ float  sq[16][8];
    __shared__ double dbuf[8];
    __shared__ bool   amLast;

    const int p    = blockIdx.x;
    const int t    = threadIdx.x;
    const int lane = t & 31;
    const int wid  = t >> 5;

#pragma unroll 1
    for (int jj = 0; jj < 4; jj++) {
        const int job = p + jj * GRIDB;
        if (job >= NJOBS) break;

        if (job >= 64) {
            // ======================= collapse tile =======================
            const int jt = job - 64;
            const int b  = jt / NTRI;
            const int s  = jt - b * NTRI;
            const int ic = TIC[s];
            const int jc = TJC[s];
            const int ibase = b * NPG + ic * TILE;
            const int jbase = b * NPG + jc * TILE;

            if (t < TILE) {
                const float* pp = pred + 3 * (size_t)(jbase + t);
                const float x = pp[0], y = pp[1], z = pp[2];
                sj[t] = make_float4(x, y, z, fmaf(x, x, fmaf(y, y, z * z)));
            }

            const int r   = lane;
            const int jlo = wid * JSLICE;

            float m2x[4], m2y[4], m2z[4], si[4];
#pragma unroll
            for (int k = 0; k < 4; k++) {
                const float* pp = pred + 3 * (size_t)(ibase + r + 32 * k);
                const float x = pp[0], y = pp[1], z = pp[2];
                si[k]  = fmaf(x, x, fmaf(y, y, z * z));
                m2x[k] = -2.0f * x;
                m2y[k] = -2.0f * y;
                m2z[k] = -2.0f * z;
            }
            __syncthreads();

            float acc[4] = {0.0f, 0.0f, 0.0f, 0.0f};
#pragma unroll
            for (int m = 0; m < JSLICE; m++) {
                const float4 q = sj[jlo + m];
#pragma unroll
                for (int k = 0; k < 4; k++) {
                    const float d2 = fmaf(m2x[k], q.x,
                                     fmaf(m2y[k], q.y,
                                     fmaf(m2z[k], q.z, si[k] + q.w)));
                    const float d  = sqrt_approx(d2);   // d2<0 -> NaN -> relu 0
                    const float e  = fmaxf(MIN_DIST - d, 0.0f);
                    acc[k] = fmaf(e, e, acc[k]);
                }
            }
            float a = (acc[0] + acc[1]) + (acc[2] + acc[3]);

            // diagonal: remove self-pairs (identical instruction sequence)
            if (ic == jc) {
#pragma unroll
                for (int k = 0; k < 4; k++) {
                    const int i  = r + 32 * k;
                    const int jd = i - jlo;
                    if (jd >= 0 && jd < JSLICE) {
                        const float4 q = sj[i];
                        const float d2 = fmaf(m2x[k], q.x,
                                         fmaf(m2y[k], q.y,
                                         fmaf(m2z[k], q.z, si[k] + q.w)));
                        const float d  = sqrt_approx(d2);
                        const float e  = fmaxf(MIN_DIST - d, 0.0f);
                        a = fmaf(-e, e, a);
                    }
                }
            }

            const float S = blockSum(a, sred);          // trailing sync protects sj reuse
            if (t == 0) g_coll[b * NTRI + s] = (ic != jc) ? 2.0f * S : S;
        } else {
            // ======================= stats (batch = job) =======================
            const int b = job;
            float px[4], py[4], pz[4], ox[4], oy[4], oz[4];
            float rsum = 0.0f;
#pragma unroll
            for (int k = 0; k < 4; k++) {
                const int idx = b * NPG + t + k * 256;
                const float* pp = pred + 3 * idx;
                const float* tt = tru  + 3 * idx;
                const float* oo = org  + 3 * idx;
                px[k] = pp[0]; py[k] = pp[1]; pz[k] = pp[2];
                const float dx = px[k] - tt[0];
                const float dy = py[k] - tt[1];
                const float dz = pz[k] - tt[2];
                rsum += dx * dx + dy * dy + dz * dz;
                ox[k] = oo[0]; oy[k] = oo[1]; oz[k] = oo[2];
            }

            float lv[14];
            lv[0]  = fminf(fminf(px[0], px[1]), fminf(px[2], px[3]));
            lv[1]  = fmaxf(fmaxf(px[0], px[1]), fmaxf(px[2], px[3]));
            lv[2]  = fminf(fminf(py[0], py[1]), fminf(py[2], py[3]));
            lv[3]  = fmaxf(fmaxf(py[0], py[1]), fmaxf(py[2], py[3]));
            lv[4]  = fminf(fminf(pz[0], pz[1]), fminf(pz[2], pz[3]));
            lv[5]  = fmaxf(fmaxf(pz[0], pz[1]), fmaxf(pz[2], pz[3]));
            lv[6]  = fminf(fminf(ox[0], ox[1]), fminf(ox[2], ox[3]));
            lv[7]  = fmaxf(fmaxf(ox[0], ox[1]), fmaxf(ox[2], ox[3]));
            lv[8]  = fminf(fminf(oy[0], oy[1]), fminf(oy[2], oy[3]));
            lv[9]  = fmaxf(fmaxf(oy[0], oy[1]), fmaxf(oy[2], oy[3]));
            lv[10] = fminf(fminf(oz[0], oz[1]), fminf(oz[2], oz[3]));
            lv[11] = fmaxf(fmaxf(oz[0], oz[1]), fmaxf(oz[2], oz[3]));
            lv[12] = pz[0] + pz[1] + pz[2] + pz[3];
            lv[13] = rsum;

#pragma unroll
            for (int i = 0; i < 14; i++) {
                float v;
                if (i < 12) v = (i & 1) ? wredMax(lv[i]) : wredMin(lv[i]);
                else        v = wredSum(lv[i]);
                if (lane == 0) sq[i][wid] = v;
            }
            __syncthreads();
            if (t < 14) {
                float a = sq[t][0];
                const bool isMin = (t < 12) && !(t & 1);
                const bool isMax = (t < 12) &&  (t & 1);
#pragma unroll
                for (int w = 1; w < 8; w++) {
                    const float u = sq[t][w];
                    a = isMin ? fminf(a, u) : (isMax ? fmaxf(a, u) : (a + u));
                }
                sq[t][0] = a;
            }
            __syncthreads();

            const float OMNZ = sq[10][0], OMXZ = sq[11][0];
            const float zr   = __fsub_rn(OMXZ, OMNZ);
            const float thlo = __fadd_rn(OMNZ, __fmul_rn(0.15f, zr));
            const float thhi = __fsub_rn(OMXZ, __fmul_rn(0.15f, zr));

            float esum = 0.0f, ecnt = 0.0f;
#pragma unroll
            for (int k = 0; k < 4; k++) {
                const bool m = (oz[k] <= thlo) || (oz[k] >= thhi);
                if (m) {
                    const float dx = px[k] - ox[k];
                    const float dy = py[k] - oy[k];
                    const float dz = pz[k] - oz[k];
                    esum += dx * dx + dy * dy + dz * dz;
                    ecnt += 1.0f;
                }
            }
            esum = wredSum(esum);
            ecnt = wredSum(ecnt);
            if (lane == 0) { sq[14][wid] = esum; sq[15][wid] = ecnt; }
            __syncthreads();

            if (t == 0) {
                float ES = 0.0f, EC = 0.0f;
#pragma unroll
                for (int w = 0; w < 8; w++) { ES += sq[14][w]; EC += sq[15][w]; }

                const float pdx = sq[1][0] - sq[0][0];
                const float pdy = sq[3][0] - sq[2][0];
                const float pdz = sq[5][0] - sq[4][0];
                const float odx = sq[7][0] - sq[6][0];
                const float ody = sq[9][0] - sq[8][0];
                const float odz = OMXZ - OMNZ;
                const float rx = (pdx - odx) / (odx + 1e-8f);
                const float ry = (pdy - ody) / (ody + 1e-8f);
                const float rz = (pdz - odz) / (odz + 1e-8f);
                const float xy_pen = fmaxf(rx - 0.02f, 0.0f) + fmaxf(ry - 0.02f, 0.0f);
                const float z_pen  = fmaxf(rz, 0.0f);

                const float zcom  = sq[12][0] * (1.0f / 1024.0f);
                const float znorm = (zcom - sq[4][0]) / ((sq[5][0] - sq[4][0]) + 1e-8f);
                const float v = nfeat[(size_t)b * NPG * NFEA + (NFEA - 3)];
                const float target = (v > 0.0f) ? 0.6f : 0.4f;
                const float dvz = znorm - target;
                const float contrib = (fabsf(v) >= 1e-6f) ? dvz * dvz : 0.0f;

                g_sb[b][0] = sq[13][0];
                g_sb[b][1] = ES;
                g_sb[b][2] = EC;
                g_sb[b][3] = xy_pen + 2.0f * z_pen;
                g_sb[b][4] = contrib;
            }
            __syncthreads();
        }
    }

    // ======================= last-block finalize =======================
    __threadfence();
    if (t == 0) {
        const unsigned int ret = atomicAdd(&g_done, 1u);
        amLast = (ret == (unsigned)(GRIDB - 1));
    }
    __syncthreads();

    if (amLast) {
        __threadfence();

        double cs = 0.0;
#pragma unroll
        for (int k = 0; k < 9; k++) cs += (double)g_coll[t + k * 256];   // 2304
        const double COLL = blockSumD(cs, dbuf);

        double r = 0.0, e = 0.0, c = 0.0, vo = 0.0, f = 0.0;
        if (t < NB) {
            r  = (double)g_sb[t][0];
            e  = (double)g_sb[t][1];
            c  = (double)g_sb[t][2];
            vo = (double)g_sb[t][3];
            f  = (double)g_sb[t][4];
        }
        const double RSUM = blockSumD(r,  dbuf);
        const double ESUM = blockSumD(e,  dbuf);
        const double ECNT = blockSumD(c,  dbuf);
        const double VSUM = blockSumD(vo, dbuf);
        const double FSUM = blockSumD(f,  dbuf);

        if (t == 0) {
            const double recon  = RSUM / (double)(NB * NPG * 3);
            const double volume = VSUM / (double)NB;
            const double elec   = ESUM / (ECNT * 3.0);
            const double coll   = COLL / ((double)NB * (double)NPG * (double)(NPG - 1));
            const double field  = FSUM / (double)NB;
            const double total  = 1.0 * recon + 10.0 * volume + 50.0 * elec
                                + 5.0 * coll + 2.0 * field;
            double vals[6] = { total, recon, volume, elec, coll, field };
            for (int i = 0; i < 6 && i < out_size; i++) out[i] = (float)vals[i];
            g_done = 0;   // reset for next graph replay
        }
    }
}

extern "C" void kernel_launch(void* const* d_in, const int* in_sizes, int n_in,
                              void* d_out, int out_size)
{
    int coord_idx[3]; int n_coord = 0;
    int nf_idx = -1, bv_idx = -1;
    for (int i = 0; i < n_in; i++) {
        if (in_sizes[i] == NB * NPG * 3) { if (n_coord < 3) coord_idx[n_coord] = i; n_coord++; }
        else if (in_sizes[i] == NB * NPG * NFEA) nf_idx = i;
        else if (in_sizes[i] == NB * NPG) bv_idx = i;
    }

    const float *pred, *tru, *org, *nf;
    if (n_coord == 3 && nf_idx >= 0) {
        if (bv_idx >= 0 && bv_idx < coord_idx[0]) {
            org  = (const float*)d_in[coord_idx[0]];
            pred = (const float*)d_in[coord_idx[1]];
            tru  = (const float*)d_in[coord_idx[2]];
        } else {
            pred = (const float*)d_in[coord_idx[0]];
            tru  = (const float*)d_in[coord_idx[1]];
            org  = (const float*)d_in[coord_idx[2]];
        }
        nf = (const float*)d_in[nf_idx];
    } else {
        pred = (const float*)d_in[0];
        tru  = (const float*)d_in[1];
        org  = (const float*)d_in[2];
        nf   = (const float*)d_in[3];
    }

    k_mega<<<GRIDB, CTHREADS>>>(pred, tru, org, nf, (float*)d_out, out_size);
}

// round 11
// speedup vs baseline: 1.6622x; 1.0197x over previous
#include <cuda_runtime.h>
#include <cstdint>

#define NB   64
#define NPG  1024
#define NFEA 8
#define MIN_DIST 2.9f

#define TILE     128
#define NTRI     36
#define CTHREADS 256
#define JSLICE   16

#define GRIDB    592                   // 4 blocks/SM * 148 SMs; 4 jobs each
#define NJOBS    (64 + NTRI * NB)      // 2368 = 592 * 4 exactly

// triangle tile decode tables (ic >= jc)
__device__ const signed char TIC[NTRI] =
    {0,1,1,2,2,2,3,3,3,3,4,4,4,4,4,5,5,5,5,5,5,
     6,6,6,6,6,6,6,7,7,7,7,7,7,7,7};
__device__ const signed char TJC[NTRI] =
    {0,0,1,0,1,2,0,1,2,3,0,1,2,3,4,0,1,2,3,4,5,
     0,1,2,3,4,5,6,0,1,2,3,4,5,6,7};

// partial slots — fully overwritten every launch
__device__ float g_coll[NTRI * NB];      // 2304
__device__ float g_sb[NB][8];
__device__ unsigned int g_done = 0;

// ---------------- reduce helpers ----------------
__device__ __forceinline__ float wredSum(float v) {
#pragma unroll
    for (int o = 16; o; o >>= 1) v += __shfl_down_sync(0xffffffffu, v, o);
    return v;
}
__device__ __forceinline__ float wredMin(float v) {
#pragma unroll
    for (int o = 16; o; o >>= 1) v = fminf(v, __shfl_down_sync(0xffffffffu, v, o));
    return v;
}
__device__ __forceinline__ float wredMax(float v) {
#pragma unroll
    for (int o = 16; o; o >>= 1) v = fmaxf(v, __shfl_down_sync(0xffffffffu, v, o));
    return v;
}
__device__ __forceinline__ float blockSum(float v, float* sbuf) {
    const int lane = threadIdx.x & 31;
    const int wid  = threadIdx.x >> 5;
    v = wredSum(v);
    if (lane == 0) sbuf[wid] = v;
    __syncthreads();
    if (wid == 0) {
        v = (lane < 8) ? sbuf[lane] : 0.0f;
        v = wredSum(v);
        if (lane == 0) sbuf[0] = v;
    }
    __syncthreads();
    float r = sbuf[0];
    __syncthreads();
    return r;
}
__device__ __forceinline__ double blockSumD(double v, double* dbuf) {
    const int lane = threadIdx.x & 31;
    const int wid  = threadIdx.x >> 5;
#pragma unroll
    for (int o = 16; o; o >>= 1) v += __shfl_down_sync(0xffffffffu, v, o);
    if (lane == 0) dbuf[wid] = v;
    __syncthreads();
    if (wid == 0) {
        v = (lane < 8) ? dbuf[lane] : 0.0;
#pragma unroll
        for (int o = 16; o; o >>= 1) v += __shfl_down_sync(0xffffffffu, v, o);
        if (lane == 0) dbuf[0] = v;
    }
    __syncthreads();
    double r = dbuf[0];
    __syncthreads();
    return r;
}
__device__ __forceinline__ float sqrt_approx(float x) {
    float d; asm("sqrt.approx.f32 %0,%1;" : "=f"(d) : "f"(x)); return d;
}

// ---------------- mega kernel: 2368 jobs over 592 blocks, 4 each ----------------
// job < 64  : stats for batch = job
// job >= 64 : triangle tile s = (job-64) % 36 of batch (job-64) / 36
__global__ __launch_bounds__(CTHREADS, 4) void k_mega(
    const float* __restrict__ pred,
    const float* __restrict__ tru,
    const float* __restrict__ org,
    const float* __restrict__ nfeat,
    float* __restrict__ out, int out_size)
{
    __shared__ float4 sj[TILE];
    __shared__ float  sred[8];
    __shared__ float  sq[16][8];
    __shared__ double dbuf[8];
    __shared__ bool   amLast;

    const int p    = blockIdx.x;
    const int t    = threadIdx.x;
    const int lane = t & 31;
    const int wid  = t >> 5;

#pragma unroll 1
    for (int jj = 0; jj < 4; jj++) {
        const int job = p + jj * GRIDB;        // < NJOBS always (2368 = 592*4)

        if (job >= 64) {
            // ======================= collapse tile =======================
            const int jt = job - 64;
            const int b  = jt / NTRI;
            const int s  = jt - b * NTRI;
            const int ic = TIC[s];
            const int jc = TJC[s];
            const int ibase = b * NPG + ic * TILE;
            const int jbase = b * NPG + jc * TILE;

            if (t < TILE) {
                const float* pp = pred + 3 * (size_t)(jbase + t);
                const float x = pp[0], y = pp[1], z = pp[2];
                sj[t] = make_float4(x, y, z, fmaf(x, x, fmaf(y, y, z * z)));
            }

            const int r   = lane;
            const int jlo = wid * JSLICE;

            float m2x[4], m2y[4], m2z[4], si[4];
#pragma unroll
            for (int k = 0; k < 4; k++) {
                const float* pp = pred + 3 * (size_t)(ibase + r + 32 * k);
                const float x = pp[0], y = pp[1], z = pp[2];
                si[k]  = fmaf(x, x, fmaf(y, y, z * z));
                m2x[k] = -2.0f * x;
                m2y[k] = -2.0f * y;
                m2z[k] = -2.0f * z;
            }
            __syncthreads();

            float acc[4] = {0.0f, 0.0f, 0.0f, 0.0f};
            float4 qn = sj[jlo];                     // prefetch iteration 0
#pragma unroll
            for (int m = 0; m < JSLICE; m++) {
                const float4 q = qn;
                if (m + 1 < JSLICE) qn = sj[jlo + m + 1];   // prefetch next
#pragma unroll
                for (int k = 0; k < 4; k++) {
                    const float d2 = fmaf(m2x[k], q.x,
                                     fmaf(m2y[k], q.y,
                                     fmaf(m2z[k], q.z, si[k] + q.w)));
                    const float d  = sqrt_approx(d2);   // d2<0 -> NaN -> relu 0
                    const float e  = fmaxf(MIN_DIST - d, 0.0f);
                    acc[k] = fmaf(e, e, acc[k]);
                }
            }
            float a = (acc[0] + acc[1]) + (acc[2] + acc[3]);

            // diagonal: remove self-pairs (identical instruction sequence)
            if (ic == jc) {
#pragma unroll
                for (int k = 0; k < 4; k++) {
                    const int i  = r + 32 * k;
                    const int jd = i - jlo;
                    if (jd >= 0 && jd < JSLICE) {
                        const float4 q = sj[i];
                        const float d2 = fmaf(m2x[k], q.x,
                                         fmaf(m2y[k], q.y,
                                         fmaf(m2z[k], q.z, si[k] + q.w)));
                        const float d  = sqrt_approx(d2);
                        const float e  = fmaxf(MIN_DIST - d, 0.0f);
                        a = fmaf(-e, e, a);
                    }
                }
            }

            const float S = blockSum(a, sred);       // trailing sync protects sj reuse
            if (t == 0) g_coll[b * NTRI + s] = (ic != jc) ? 2.0f * S : S;
        } else {
            // ======================= stats (batch = job) =======================
            const int b = job;
            float px[4], py[4], pz[4], ox[4], oy[4], oz[4];
            float rsum = 0.0f;
#pragma unroll
            for (int k = 0; k < 4; k++) {
                const int idx = b * NPG + t + k * 256;
                const float* pp = pred + 3 * idx;
                const float* tt = tru  + 3 * idx;
                const float* oo = org  + 3 * idx;
                px[k] = pp[0]; py[k] = pp[1]; pz[k] = pp[2];
                const float dx = px[k] - tt[0];
                const float dy = py[k] - tt[1];
                const float dz = pz[k] - tt[2];
                rsum += dx * dx + dy * dy + dz * dz;
                ox[k] = oo[0]; oy[k] = oo[1]; oz[k] = oo[2];
            }

            float lv[14];
            lv[0]  = fminf(fminf(px[0], px[1]), fminf(px[2], px[3]));
            lv[1]  = fmaxf(fmaxf(px[0], px[1]), fmaxf(px[2], px[3]));
            lv[2]  = fminf(fminf(py[0], py[1]), fminf(py[2], py[3]));
            lv[3]  = fmaxf(fmaxf(py[0], py[1]), fmaxf(py[2], py[3]));
            lv[4]  = fminf(fminf(pz[0], pz[1]), fminf(pz[2], pz[3]));
            lv[5]  = fmaxf(fmaxf(pz[0], pz[1]), fmaxf(pz[2], pz[3]));
            lv[6]  = fminf(fminf(ox[0], ox[1]), fminf(ox[2], ox[3]));
            lv[7]  = fmaxf(fmaxf(ox[0], ox[1]), fmaxf(ox[2], ox[3]));
            lv[8]  = fminf(fminf(oy[0], oy[1]), fminf(oy[2], oy[3]));
            lv[9]  = fmaxf(fmaxf(oy[0], oy[1]), fmaxf(oy[2], oy[3]));
            lv[10] = fminf(fminf(oz[0], oz[1]), fminf(oz[2], oz[3]));
            lv[11] = fmaxf(fmaxf(oz[0], oz[1]), fmaxf(oz[2], oz[3]));
            lv[12] = pz[0] + pz[1] + pz[2] + pz[3];
            lv[13] = rsum;

#pragma unroll
            for (int i = 0; i < 14; i++) {
                float v;
                if (i < 12) v = (i & 1) ? wredMax(lv[i]) : wredMin(lv[i]);
                else        v = wredSum(lv[i]);
                if (lane == 0) sq[i][wid] = v;
            }
            __syncthreads();
            if (t < 14) {
                float a = sq[t][0];
                const bool isMin = (t < 12) && !(t & 1);
                const bool isMax = (t < 12) &&  (t & 1);
#pragma unroll
                for (int w = 1; w < 8; w++) {
                    const float u = sq[t][w];
                    a = isMin ? fminf(a, u) : (isMax ? fmaxf(a, u) : (a + u));
                }
                sq[t][0] = a;
            }
            __syncthreads();

            const float OMNZ = sq[10][0], OMXZ = sq[11][0];
            const float zr   = __fsub_rn(OMXZ, OMNZ);
            const float thlo = __fadd_rn(OMNZ, __fmul_rn(0.15f, zr));
            const float thhi = __fsub_rn(OMXZ, __fmul_rn(0.15f, zr));

            float esum = 0.0f, ecnt = 0.0f;
#pragma unroll
            for (int k = 0; k < 4; k++) {
                const bool m = (oz[k] <= thlo) || (oz[k] >= thhi);
                if (m) {
                    const float dx = px[k] - ox[k];
                    const float dy = py[k] - oy[k];
                    const float dz = pz[k] - oz[k];
                    esum += dx * dx + dy * dy + dz * dz;
                    ecnt += 1.0f;
                }
            }
            esum = wredSum(esum);
            ecnt = wredSum(ecnt);
            if (lane == 0) { sq[14][wid] = esum; sq[15][wid] = ecnt; }
            __syncthreads();

            if (t == 0) {
                float ES = 0.0f, EC = 0.0f;
#pragma unroll
                for (int w = 0; w < 8; w++) { ES += sq[14][w]; EC += sq[15][w]; }

                const float pdx = sq[1][0] - sq[0][0];
                const float pdy = sq[3][0] - sq[2][0];
                const float pdz = sq[5][0] - sq[4][0];
                const float odx = sq[7][0] - sq[6][0];
                const float ody = sq[9][0] - sq[8][0];
                const float odz = OMXZ - OMNZ;
                const float rx = (pdx - odx) / (odx + 1e-8f);
                const float ry = (pdy - ody) / (ody + 1e-8f);
                const float rz = (pdz - odz) / (odz + 1e-8f);
                const float xy_pen = fmaxf(rx - 0.02f, 0.0f) + fmaxf(ry - 0.02f, 0.0f);
                const float z_pen  = fmaxf(rz, 0.0f);

                const float zcom  = sq[12][0] * (1.0f / 1024.0f);
                const float znorm = (zcom - sq[4][0]) / ((sq[5][0] - sq[4][0]) + 1e-8f);
                const float v = nfeat[(size_t)b * NPG * NFEA + (NFEA - 3)];
                const float target = (v > 0.0f) ? 0.6f : 0.4f;
                const float dvz = znorm - target;
                const float contrib = (fabsf(v) >= 1e-6f) ? dvz * dvz : 0.0f;

                g_sb[b][0] = sq[13][0];
                g_sb[b][1] = ES;
                g_sb[b][2] = EC;
                g_sb[b][3] = xy_pen + 2.0f * z_pen;
                g_sb[b][4] = contrib;
            }
            __syncthreads();
        }
    }

    // ======================= last-block finalize =======================
    __threadfence();
    if (t == 0) {
        const unsigned int ret = atomicAdd(&g_done, 1u);
        amLast = (ret == (unsigned)(GRIDB - 1));
    }
    __syncthreads();

    if (amLast) {
        __threadfence();

        double cs = 0.0;
#pragma unroll
        for (int k = 0; k < 9; k++) cs += (double)g_coll[t + k * 256];   // 2304
        const double COLL = blockSumD(cs, dbuf);

        double r = 0.0, e = 0.0, c = 0.0, vo = 0.0, f = 0.0;
        if (t < NB) {
            r  = (double)g_sb[t][0];
            e  = (double)g_sb[t][1];
            c  = (double)g_sb[t][2];
            vo = (double)g_sb[t][3];
            f  = (double)g_sb[t][4];
        }
        const double RSUM = blockSumD(r,  dbuf);
        const double ESUM = blockSumD(e,  dbuf);
        const double ECNT = blockSumD(c,  dbuf);
        const double VSUM = blockSumD(vo, dbuf);
        const double FSUM = blockSumD(f,  dbuf);

        if (t == 0) {
            const double recon  = RSUM / (double)(NB * NPG * 3);
            const double volume = VSUM / (double)NB;
            const double elec   = ESUM / (ECNT * 3.0);
            const double coll   = COLL / ((double)NB * (double)NPG * (double)(NPG - 1));
            const double field  = FSUM / (double)NB;
            const double total  = 1.0 * recon + 10.0 * volume + 50.0 * elec
                                + 5.0 * coll + 2.0 * field;
            double vals[6] = { total, recon, volume, elec, coll, field };
            for (int i = 0; i < 6 && i < out_size; i++) out[i] = (float)vals[i];
            g_done = 0;   // reset for next graph replay
        }
    }
}

extern "C" void kernel_launch(void* const* d_in, const int* in_sizes, int n_in,
                              void* d_out, int out_size)
{
    int coord_idx[3]; int n_coord = 0;
    int nf_idx = -1, bv_idx = -1;
    for (int i = 0; i < n_in; i++) {
        if (in_sizes[i] == NB * NPG * 3) { if (n_coord < 3) coord_idx[n_coord] = i; n_coord++; }
        else if (in_sizes[i] == NB * NPG * NFEA) nf_idx = i;
        else if (in_sizes[i] == NB * NPG) bv_idx = i;
    }

    const float *pred, *tru, *org, *nf;
    if (n_coord == 3 && nf_idx >= 0) {
        if (bv_idx >= 0 && bv_idx < coord_idx[0]) {
            org  = (const float*)d_in[coord_idx[0]];
            pred = (const float*)d_in[coord_idx[1]];
            tru  = (const float*)d_in[coord_idx[2]];
        } else {
            pred = (const float*)d_in[coord_idx[0]];
            tru  = (const float*)d_in[coord_idx[1]];
            org  = (const float*)d_in[coord_idx[2]];
        }
        nf = (const float*)d_in[nf_idx];
    } else {
        pred = (const float*)d_in[0];
        tru  = (const float*)d_in[1];
        org  = (const float*)d_in[2];
        nf   = (const float*)d_in[3];
    }

    k_mega<<<GRIDB, CTHREADS>>>(pred, tru, org, nf, (float*)d_out, out_size);
}

// round 12
// speedup vs baseline: 1.7454x; 1.0501x over previous
#include <cuda_runtime.h>
#include <cstdint>

#define NB   64
#define NPG  1024
#define NFEA 8
#define MIN_DIST 2.9f

#define TILE     128
#define NCHUNK   (NPG / TILE)                  // 8
#define NTRI     (NCHUNK * (NCHUNK + 1) / 2)   // 36
#define CTHREADS 256
#define NBLOCKS  ((NTRI + 1) * NB)             // 2368
#define JSLICE   16

typedef unsigned long long u64;

// triangle tile decode tables (ic >= jc)
__device__ const signed char TIC[NTRI] =
    {0,1,1,2,2,2,3,3,3,3,4,4,4,4,4,5,5,5,5,5,5,
     6,6,6,6,6,6,6,7,7,7,7,7,7,7,7};
__device__ const signed char TJC[NTRI] =
    {0,0,1,0,1,2,0,1,2,3,0,1,2,3,4,0,1,2,3,4,5,
     0,1,2,3,4,5,6,0,1,2,3,4,5,6,7};

// partial slots — fully overwritten every launch
__device__ float g_coll[NTRI * NB];      // 2304
__device__ float g_sb[NB][8];
__device__ unsigned int g_done = 0;

// ---------------- packed f32x2 helpers ----------------
__device__ __forceinline__ u64 fma2(u64 a, u64 b, u64 c) {
    u64 d; asm("fma.rn.f32x2 %0,%1,%2,%3;" : "=l"(d) : "l"(a), "l"(b), "l"(c)); return d;
}
__device__ __forceinline__ u64 add2(u64 a, u64 b) {
    u64 d; asm("add.rn.f32x2 %0,%1,%2;" : "=l"(d) : "l"(a), "l"(b)); return d;
}
__device__ __forceinline__ u64 pack2(float lo, float hi) {
    u64 r; asm("mov.b64 %0,{%1,%2};" : "=l"(r) : "f"(lo), "f"(hi)); return r;
}
__device__ __forceinline__ void unpack2(float& lo, float& hi, u64 v) {
    asm("mov.b64 {%0,%1},%2;" : "=f"(lo), "=f"(hi) : "l"(v));
}
__device__ __forceinline__ u64 bcast2(float f) {
    u64 r; asm("mov.b64 %0,{%1,%1};" : "=l"(r) : "f"(f)); return r;
}
__device__ __forceinline__ float sqrt_approx(float x) {
    float d; asm("sqrt.approx.f32 %0,%1;" : "=f"(d) : "f"(x)); return d;
}

// ---------------- reduce helpers ----------------
__device__ __forceinline__ float wredSum(float v) {
#pragma unroll
    for (int o = 16; o; o >>= 1) v += __shfl_down_sync(0xffffffffu, v, o);
    return v;
}
__device__ __forceinline__ float wredMin(float v) {
#pragma unroll
    for (int o = 16; o; o >>= 1) v = fminf(v, __shfl_down_sync(0xffffffffu, v, o));
    return v;
}
__device__ __forceinline__ float wredMax(float v) {
#pragma unroll
    for (int o = 16; o; o >>= 1) v = fmaxf(v, __shfl_down_sync(0xffffffffu, v, o));
    return v;
}
__device__ __forceinline__ float blockSum(float v, float* sbuf) {
    const int lane = threadIdx.x & 31;
    const int wid  = threadIdx.x >> 5;
    v = wredSum(v);
    if (lane == 0) sbuf[wid] = v;
    __syncthreads();
    if (wid == 0) {
        v = (lane < 8) ? sbuf[lane] : 0.0f;
        v = wredSum(v);
        if (lane == 0) sbuf[0] = v;
    }
    __syncthreads();
    float r = sbuf[0];
    __syncthreads();
    return r;
}
__device__ __forceinline__ double blockSumD(double v, double* dbuf) {
    const int lane = threadIdx.x & 31;
    const int wid  = threadIdx.x >> 5;
#pragma unroll
    for (int o = 16; o; o >>= 1) v += __shfl_down_sync(0xffffffffu, v, o);
    if (lane == 0) dbuf[wid] = v;
    __syncthreads();
    if (wid == 0) {
        v = (lane < 8) ? dbuf[lane] : 0.0;
#pragma unroll
        for (int o = 16; o; o >>= 1) v += __shfl_down_sync(0xffffffffu, v, o);
        if (lane == 0) dbuf[0] = v;
    }
    __syncthreads();
    double r = dbuf[0];
    __syncthreads();
    return r;
}

// ---------------- fused kernel (R7 structure, packed f32x2 core) ----------------
// grid (NTRI+1, NB), 256 threads.
__global__ __launch_bounds__(CTHREADS) void k_fused(
    const float* __restrict__ pred,
    const float* __restrict__ tru,
    const float* __restrict__ org,
    const float* __restrict__ nfeat,
    float* __restrict__ out, int out_size)
{
    __shared__ u64   sjp[TILE][4];   // per j-point: (x,x),(y,y),(z,z),(w,w)
    __shared__ float sred[8];
    __shared__ float sq[16][8];
    __shared__ double dbuf[8];
    __shared__ bool  amLast;

    const int b  = blockIdx.y;
    const int bx = blockIdx.x;
    const int t  = threadIdx.x;
    const int lane = t & 31;
    const int wid  = t >> 5;

    if (bx < NTRI) {
        // ======================= collapse tile =======================
        const int ic = TIC[bx];
        const int jc = TJC[bx];
        const int ibase = b * NPG + ic * TILE;
        const int jbase = b * NPG + jc * TILE;

        if (t < TILE) {
            const float* pp = pred + 3 * (size_t)(jbase + t);
            const float x = pp[0], y = pp[1], z = pp[2];
            const float w = fmaf(x, x, fmaf(y, y, z * z));
            sjp[t][0] = bcast2(x);
            sjp[t][1] = bcast2(y);
            sjp[t][2] = bcast2(z);
            sjp[t][3] = bcast2(w);
        }

        // 4 i-rows per thread (lane, lane+32, lane+64, lane+96); j-slice [wid*16, +16)
        const int r   = lane;
        const int jlo = wid * JSLICE;

        float m2x[4], m2y[4], m2z[4], si[4];
#pragma unroll
        for (int k = 0; k < 4; k++) {
            const float* pp = pred + 3 * (size_t)(ibase + r + 32 * k);
            const float x = pp[0], y = pp[1], z = pp[2];
            si[k]  = fmaf(x, x, fmaf(y, y, z * z));
            m2x[k] = -2.0f * x;
            m2y[k] = -2.0f * y;
            m2z[k] = -2.0f * z;
        }
        // pack i-side once per job
        const u64 X01 = pack2(m2x[0], m2x[1]), X23 = pack2(m2x[2], m2x[3]);
        const u64 Y01 = pack2(m2y[0], m2y[1]), Y23 = pack2(m2y[2], m2y[3]);
        const u64 Z01 = pack2(m2z[0], m2z[1]), Z23 = pack2(m2z[2], m2z[3]);
        const u64 S01 = pack2(si[0],  si[1]),  S23 = pack2(si[2],  si[3]);
        __syncthreads();

        float acc0 = 0.0f, acc1 = 0.0f, acc2 = 0.0f, acc3 = 0.0f;
#pragma unroll
        for (int m = 0; m < JSLICE; m++) {
            const u64 qx2 = sjp[jlo + m][0];
            const u64 qy2 = sjp[jlo + m][1];
            const u64 qz2 = sjp[jlo + m][2];
            const u64 qw2 = sjp[jlo + m][3];

            // pairs k=0,1: d2 chain order = (S+qw), +z, +y, +x
            {
                const u64 d2p = fma2(X01, qx2, fma2(Y01, qy2, fma2(Z01, qz2, add2(S01, qw2))));
                float a, c; unpack2(a, c, d2p);
                const float da = sqrt_approx(a);   // d2<0 -> NaN -> relu 0
                const float dc = sqrt_approx(c);
                const float ea = fmaxf(MIN_DIST - da, 0.0f);
                const float ec = fmaxf(MIN_DIST - dc, 0.0f);
                acc0 = fmaf(ea, ea, acc0);
                acc1 = fmaf(ec, ec, acc1);
            }
            // pairs k=2,3
            {
                const u64 d2p = fma2(X23, qx2, fma2(Y23, qy2, fma2(Z23, qz2, add2(S23, qw2))));
                float a, c; unpack2(a, c, d2p);
                const float da = sqrt_approx(a);
                const float dc = sqrt_approx(c);
                const float ea = fmaxf(MIN_DIST - da, 0.0f);
                const float ec = fmaxf(MIN_DIST - dc, 0.0f);
                acc2 = fmaf(ea, ea, acc2);
                acc3 = fmaf(ec, ec, acc3);
            }
        }
        float a = (acc0 + acc1) + (acc2 + acc3);

        // diagonal: remove self-pairs. Scalar chain with identical evaluation
        // order ((si+qw), +z, +y, +x) — f32x2 halves round identically to
        // scalar FFMA -> exact cancellation (NaN-safe: both paths produce 0).
        if (ic == jc) {
#pragma unroll
            for (int k = 0; k < 4; k++) {
                const int i  = r + 32 * k;
                const int jd = i - jlo;
                if (jd >= 0 && jd < JSLICE) {
                    const float qx = __uint_as_float((unsigned)(sjp[i][0] & 0xFFFFFFFFu));
                    const float qy = __uint_as_float((unsigned)(sjp[i][1] & 0xFFFFFFFFu));
                    const float qz = __uint_as_float((unsigned)(sjp[i][2] & 0xFFFFFFFFu));
                    const float qw = __uint_as_float((unsigned)(sjp[i][3] & 0xFFFFFFFFu));
                    const float d2 = fmaf(m2x[k], qx,
                                     fmaf(m2y[k], qy,
                                     fmaf(m2z[k], qz, si[k] + qw)));
                    const float d  = sqrt_approx(d2);
                    const float e  = fmaxf(MIN_DIST - d, 0.0f);
                    a = fmaf(-e, e, a);
                }
            }
        }

        const float S = blockSum(a, sred);
        if (t == 0) g_coll[b * NTRI + bx] = (ic != jc) ? 2.0f * S : S;  // x2 exact
    } else {
        // ======================= stats =======================
        float px[4], py[4], pz[4], ox[4], oy[4], oz[4];
        float rsum = 0.0f;
#pragma unroll
        for (int k = 0; k < 4; k++) {
            const int idx = b * NPG + t + k * 256;
            const float* pp = pred + 3 * idx;
            const float* tt = tru  + 3 * idx;
            const float* oo = org  + 3 * idx;
            px[k] = pp[0]; py[k] = pp[1]; pz[k] = pp[2];
            const float dx = px[k] - tt[0];
            const float dy = py[k] - tt[1];
            const float dz = pz[k] - tt[2];
            rsum += dx * dx + dy * dy + dz * dz;
            ox[k] = oo[0]; oy[k] = oo[1]; oz[k] = oo[2];
        }

        float lv[14];
        lv[0]  = fminf(fminf(px[0], px[1]), fminf(px[2], px[3]));
        lv[1]  = fmaxf(fmaxf(px[0], px[1]), fmaxf(px[2], px[3]));
        lv[2]  = fminf(fminf(py[0], py[1]), fminf(py[2], py[3]));
        lv[3]  = fmaxf(fmaxf(py[0], py[1]), fmaxf(py[2], py[3]));
        lv[4]  = fminf(fminf(pz[0], pz[1]), fminf(pz[2], pz[3]));
        lv[5]  = fmaxf(fmaxf(pz[0], pz[1]), fmaxf(pz[2], pz[3]));
        lv[6]  = fminf(fminf(ox[0], ox[1]), fminf(ox[2], ox[3]));
        lv[7]  = fmaxf(fmaxf(ox[0], ox[1]), fmaxf(ox[2], ox[3]));
        lv[8]  = fminf(fminf(oy[0], oy[1]), fminf(oy[2], oy[3]));
        lv[9]  = fmaxf(fmaxf(oy[0], oy[1]), fmaxf(oy[2], oy[3]));
        lv[10] = fminf(fminf(oz[0], oz[1]), fminf(oz[2], oz[3]));
        lv[11] = fmaxf(fmaxf(oz[0], oz[1]), fmaxf(oz[2], oz[3]));
        lv[12] = pz[0] + pz[1] + pz[2] + pz[3];
        lv[13] = rsum;

#pragma unroll
        for (int i = 0; i < 14; i++) {
            float v;
            if (i < 12) v = (i & 1) ? wredMax(lv[i]) : wredMin(lv[i]);
            else        v = wredSum(lv[i]);
            if (lane == 0) sq[i][wid] = v;
        }
        __syncthreads();
        if (t < 14) {
            float a = sq[t][0];
            const bool isMin = (t < 12) && !(t & 1);
            const bool isMax = (t < 12) &&  (t & 1);
#pragma unroll
            for (int w = 1; w < 8; w++) {
                const float u = sq[t][w];
                a = isMin ? fminf(a, u) : (isMax ? fmaxf(a, u) : (a + u));
            }
            sq[t][0] = a;
        }
        __syncthreads();

        const float OMNZ = sq[10][0], OMXZ = sq[11][0];
        const float zr   = __fsub_rn(OMXZ, OMNZ);
        const float thlo = __fadd_rn(OMNZ, __fmul_rn(0.15f, zr));
        const float thhi = __fsub_rn(OMXZ, __fmul_rn(0.15f, zr));

        float esum = 0.0f, ecnt = 0.0f;
#pragma unroll
        for (int k = 0; k < 4; k++) {
            const bool m = (oz[k] <= thlo) || (oz[k] >= thhi);
            if (m) {
                const float dx = px[k] - ox[k];
                const float dy = py[k] - oy[k];
                const float dz = pz[k] - oz[k];
                esum += dx * dx + dy * dy + dz * dz;
                ecnt += 1.0f;
            }
        }
        esum = wredSum(esum);
        ecnt = wredSum(ecnt);
        if (lane == 0) { sq[14][wid] = esum; sq[15][wid] = ecnt; }
        __syncthreads();

        if (t == 0) {
            float ES = 0.0f, EC = 0.0f;
#pragma unroll
            for (int w = 0; w < 8; w++) { ES += sq[14][w]; EC += sq[15][w]; }

            const float pdx = sq[1][0] - sq[0][0];
            const float pdy = sq[3][0] - sq[2][0];
            const float pdz = sq[5][0] - sq[4][0];
            const float odx = sq[7][0] - sq[6][0];
            const float ody = sq[9][0] - sq[8][0];
            const float odz = OMXZ - OMNZ;
            const float rx = (pdx - odx) / (odx + 1e-8f);
            const float ry = (pdy - ody) / (ody + 1e-8f);
            const float rz = (pdz - odz) / (odz + 1e-8f);
            const float xy_pen = fmaxf(rx - 0.02f, 0.0f) + fmaxf(ry - 0.02f, 0.0f);
            const float z_pen  = fmaxf(rz, 0.0f);

            const float zcom  = sq[12][0] * (1.0f / 1024.0f);
            const float znorm = (zcom - sq[4][0]) / ((sq[5][0] - sq[4][0]) + 1e-8f);
            const float v = nfeat[(size_t)b * NPG * NFEA + (NFEA - 3)];
            const float target = (v > 0.0f) ? 0.6f : 0.4f;
            const float dvz = znorm - target;
            const float contrib = (fabsf(v) >= 1e-6f) ? dvz * dvz : 0.0f;

            g_sb[b][0] = sq[13][0];
            g_sb[b][1] = ES;
            g_sb[b][2] = EC;
            g_sb[b][3] = xy_pen + 2.0f * z_pen;
            g_sb[b][4] = contrib;
        }
        __syncthreads();
    }

    // ======================= last-block finalize =======================
    __threadfence();
    if (t == 0) {
        const unsigned int ret = atomicAdd(&g_done, 1u);
        amLast = (ret == (unsigned)(NBLOCKS - 1));
    }
    __syncthreads();

    if (amLast) {
        __threadfence();

        double cs = 0.0;
#pragma unroll
        for (int k = 0; k < 9; k++) cs += (double)g_coll[t + k * 256];   // 2304
        const double COLL = blockSumD(cs, dbuf);

        double r = 0.0, e = 0.0, c = 0.0, vo = 0.0, f = 0.0;
        if (t < NB) {
            r  = (double)g_sb[t][0];
            e  = (double)g_sb[t][1];
            c  = (double)g_sb[t][2];
            vo = (double)g_sb[t][3];
            f  = (double)g_sb[t][4];
        }
        const double RSUM = blockSumD(r,  dbuf);
        const double ESUM = blockSumD(e,  dbuf);
        const double ECNT = blockSumD(c,  dbuf);
        const double VSUM = blockSumD(vo, dbuf);
        const double FSUM = blockSumD(f,  dbuf);

        if (t == 0) {
            const double recon  = RSUM / (double)(NB * NPG * 3);
            const double volume = VSUM / (double)NB;
            const double elec   = ESUM / (ECNT * 3.0);
            const double coll   = COLL / ((double)NB * (double)NPG * (double)(NPG - 1));
            const double field  = FSUM / (double)NB;
            const double total  = 1.0 * recon + 10.0 * volume + 50.0 * elec
                                + 5.0 * coll + 2.0 * field;
            double vals[6] = { total, recon, volume, elec, coll, field };
            for (int i = 0; i < 6 && i < out_size; i++) out[i] = (float)vals[i];
            g_done = 0;   // reset for next graph replay
        }
    }
}

extern "C" void kernel_launch(void* const* d_in, const int* in_sizes, int n_in,
                              void* d_out, int out_size)
{
    int coord_idx[3]; int n_coord = 0;
    int nf_idx = -1, bv_idx = -1;
    for (int i = 0; i < n_in; i++) {
        if (in_sizes[i] == NB * NPG * 3) { if (n_coord < 3) coord_idx[n_coord] = i; n_coord++; }
        else if (in_sizes[i] == NB * NPG * NFEA) nf_idx = i;
        else if (in_sizes[i] == NB * NPG) bv_idx = i;
    }

    const float *pred, *tru, *org, *nf;
    if (n_coord == 3 && nf_idx >= 0) {
        if (bv_idx >= 0 && bv_idx < coord_idx[0]) {
            org  = (const float*)d_in[coord_idx[0]];
            pred = (const float*)d_in[coord_idx[1]];
            tru  = (const float*)d_in[coord_idx[2]];
        } else {
            pred = (const float*)d_in[coord_idx[0]];
            tru  = (const float*)d_in[coord_idx[1]];
            org  = (const float*)d_in[coord_idx[2]];
        }
        nf = (const float*)d_in[nf_idx];
    } else {
        pred = (const float*)d_in[0];
        tru  = (const float*)d_in[1];
        org  = (const float*)d_in[2];
        nf   = (const float*)d_in[3];
    }

    k_fused<<<dim3(NTRI + 1, NB), CTHREADS>>>(pred, tru, org, nf,
                                              (float*)d_out, out_size);
}